// round 1
// baseline (speedup 1.0000x reference)
#include <cuda_runtime.h>
#include <math.h>

// Pipeline:
//  inputs (metadata order):
//   0 sensor_input  [1,3,64,64]  (12288 f32)
//   1 initial_pose  [3]
//   2 initial_angles[2]
//   3 wheel_ticks   [2]
//   4 conv_w        [4,3,4,4]    (192)
//   5 conv_b        [4]
//   6 lin_w         [2,256]      (512)
//   7 lin_b         [2]
//  output: trajectory [19,2] then new_pose [3]  -> 41 f32

__global__ __launch_bounds__(256, 1)
void robot_fused_kernel(const float* __restrict__ x,
                        const float* __restrict__ pose,
                        const float* __restrict__ angles0,
                        const float* __restrict__ ticks,
                        const float* __restrict__ cw,
                        const float* __restrict__ cb,
                        const float* __restrict__ lw,
                        const float* __restrict__ lb,
                        float* __restrict__ out)
{
    __shared__ float red0[8];
    __shared__ float red1[8];

    const int tid = threadIdx.x;          // 0..255, one pooled output each
    const int c  = tid >> 6;              // 0..3
    const int ph = (tid >> 3) & 7;        // 0..7
    const int pw = tid & 7;               // 0..7

    // Preload this channel's 3x4x4 filter into registers
    float w[3][4][4];
#pragma unroll
    for (int ic = 0; ic < 3; ic++)
#pragma unroll
        for (int kh = 0; kh < 4; kh++)
#pragma unroll
            for (int kw = 0; kw < 4; kw++)
                w[ic][kh][kw] = cw[((c * 3 + ic) * 4 + kh) * 4 + kw];

    const float bias = cb[c];

    // conv (stride 4, pad 1) + relu + 2x2 maxpool for this pooled cell
    float mx = 0.0f;  // relu floor is 0, so max starts at 0
#pragma unroll
    for (int dy = 0; dy < 2; dy++) {
#pragma unroll
        for (int dx = 0; dx < 2; dx++) {
            const int oh = 2 * ph + dy;       // 0..15
            const int ow = 2 * pw + dx;       // 0..15
            float acc = bias;
#pragma unroll
            for (int ic = 0; ic < 3; ic++) {
                const float* xp = x + ic * 4096;
#pragma unroll
                for (int kh = 0; kh < 4; kh++) {
                    const int ih = oh * 4 - 1 + kh;
                    if (ih < 0 || ih > 63) continue;
#pragma unroll
                    for (int kw = 0; kw < 4; kw++) {
                        const int iw = ow * 4 - 1 + kw;
                        if (iw < 0 || iw > 63) continue;
                        acc = fmaf(xp[ih * 64 + iw], w[ic][kh][kw], acc);
                    }
                }
            }
            mx = fmaxf(mx, fmaxf(acc, 0.0f));
        }
    }

    // linear 256 -> 2: per-thread partials, warp shuffle reduce, smem combine
    float p0 = mx * lw[tid];
    float p1 = mx * lw[256 + tid];
#pragma unroll
    for (int o = 16; o > 0; o >>= 1) {
        p0 += __shfl_down_sync(0xffffffffu, p0, o);
        p1 += __shfl_down_sync(0xffffffffu, p1, o);
    }
    if ((tid & 31) == 0) {
        red0[tid >> 5] = p0;
        red1[tid >> 5] = p1;
    }
    __syncthreads();

    if (tid == 0) {
        float t0 = lb[0], t1 = lb[1];
#pragma unroll
        for (int i = 0; i < 8; i++) { t0 += red0[i]; t1 += red1[i]; }

        // ---- IK: 9 damped-Newton steps (double for stability) ----
        const double tx = (double)t0, ty = (double)t1;
        double q1 = (double)angles0[0];
        double q2 = (double)angles0[1];
#pragma unroll
        for (int s = 0; s < 9; s++) {
            double s1 = sin(q1), c1 = cos(q1);
            double s12 = sin(q1 + q2), c12 = cos(q1 + q2);
            double px = c1 + c12;        // L1 = L2 = 1
            double py = s1 + s12;
            double ex = tx - px, ey = ty - py;
            double j11 = -s1 - s12, j12 = -s12;
            double j21 =  c1 + c12, j22 =  c12;
            double det = j11 * j22 - j12 * j21;
            double inv = 1.0 / (det + 1e-6);
            q1 += (j22 * ex - j12 * ey) * inv;   // ALPHA = 1
            q2 += (-j21 * ex + j11 * ey) * inv;
        }

        // ---- trajectory: start -> mid(-0.2,0) -> end(0,-0.1), 10+9 points ----
        double sx = cos(q1) + cos(q1 + q2);
        double sy = sin(q1) + sin(q1 + q2);
        double mx0 = sx - 0.2, my0 = sy;
        double ex0 = mx0,      ey0 = my0 - 0.1;
#pragma unroll
        for (int k = 0; k < 10; k++) {
            double t = (double)k / 9.0;
            out[2 * k]     = (float)(sx * (1.0 - t) + mx0 * t);
            out[2 * k + 1] = (float)(sy * (1.0 - t) + my0 * t);
        }
#pragma unroll
        for (int k = 1; k < 10; k++) {
            double t = (double)k / 9.0;
            out[2 * (9 + k)]     = (float)(mx0 * (1.0 - t) + ex0 * t);
            out[2 * (9 + k) + 1] = (float)(my0 * (1.0 - t) + ey0 * t);
        }

        // ---- odometry ----
        double dl = (double)ticks[0] * 1e-4;
        double dr = (double)ticks[1] * 1e-4;
        double dc = 0.5 * (dl + dr);
        double dth = (dr - dl) / 0.5;
        double avg = (double)pose[2] + 0.5 * dth;
        out[38] = (float)((double)pose[0] + dc * cos(avg));
        out[39] = (float)((double)pose[1] + dc * sin(avg));
        out[40] = (float)((double)pose[2] + dth);
    }
}

extern "C" void kernel_launch(void* const* d_in, const int* in_sizes, int n_in,
                              void* d_out, int out_size)
{
    const float* x       = (const float*)d_in[0];
    const float* pose    = (const float*)d_in[1];
    const float* angles0 = (const float*)d_in[2];
    const float* ticks   = (const float*)d_in[3];
    const float* cw      = (const float*)d_in[4];
    const float* cb      = (const float*)d_in[5];
    const float* lw      = (const float*)d_in[6];
    const float* lb      = (const float*)d_in[7];
    float* out = (float*)d_out;

    robot_fused_kernel<<<1, 256>>>(x, pose, angles0, ticks, cw, cb, lw, lb, out);
}

// round 2
// speedup vs baseline: 3.1571x; 3.1571x over previous
#include <cuda_runtime.h>
#include <math.h>

// Pipeline (all fp32; reference is fp32 JAX, tol 1e-3):
//  inputs (metadata order):
//   0 sensor_input  [1,3,64,64]  (12288 f32)
//   1 initial_pose  [3]
//   2 initial_angles[2]
//   3 wheel_ticks   [2]
//   4 conv_w        [4,3,4,4]    (192)
//   5 conv_b        [4]
//   6 lin_w         [2,256]      (512)
//   7 lin_b         [2]
//  output: trajectory [19,2] then new_pose [3]  -> 41 f32

__global__ __launch_bounds__(256, 1)
void robot_fused_kernel(const float* __restrict__ x,
                        const float* __restrict__ pose,
                        const float* __restrict__ angles0,
                        const float* __restrict__ ticks,
                        const float* __restrict__ cw,
                        const float* __restrict__ cb,
                        const float* __restrict__ lw,
                        const float* __restrict__ lb,
                        float* __restrict__ out)
{
    __shared__ float red0[8];
    __shared__ float red1[8];

    const int tid = threadIdx.x;          // 0..255, one pooled output each
    const int c  = tid >> 6;              // 0..3
    const int ph = (tid >> 3) & 7;        // 0..7
    const int pw = tid & 7;               // 0..7

    // Preload this channel's 3x4x4 filter into registers
    float w[3][4][4];
#pragma unroll
    for (int ic = 0; ic < 3; ic++)
#pragma unroll
        for (int kh = 0; kh < 4; kh++)
#pragma unroll
            for (int kw = 0; kw < 4; kw++)
                w[ic][kh][kw] = cw[((c * 3 + ic) * 4 + kh) * 4 + kw];

    const float bias = cb[c];

    // conv (stride 4, pad 1) + relu + 2x2 maxpool for this pooled cell
    float mx = 0.0f;  // relu floor is 0, so max starts at 0
#pragma unroll
    for (int dy = 0; dy < 2; dy++) {
#pragma unroll
        for (int dx = 0; dx < 2; dx++) {
            const int oh = 2 * ph + dy;       // 0..15
            const int ow = 2 * pw + dx;       // 0..15
            float acc = bias;
#pragma unroll
            for (int ic = 0; ic < 3; ic++) {
                const float* xp = x + ic * 4096;
#pragma unroll
                for (int kh = 0; kh < 4; kh++) {
                    const int ih = oh * 4 - 1 + kh;
                    if (ih < 0 || ih > 63) continue;
#pragma unroll
                    for (int kw = 0; kw < 4; kw++) {
                        const int iw = ow * 4 - 1 + kw;
                        if (iw < 0 || iw > 63) continue;
                        acc = fmaf(xp[ih * 64 + iw], w[ic][kh][kw], acc);
                    }
                }
            }
            mx = fmaxf(mx, fmaxf(acc, 0.0f));
        }
    }

    // linear 256 -> 2: per-thread partials, warp shuffle reduce, smem combine
    float p0 = mx * lw[tid];
    float p1 = mx * lw[256 + tid];
#pragma unroll
    for (int o = 16; o > 0; o >>= 1) {
        p0 += __shfl_down_sync(0xffffffffu, p0, o);
        p1 += __shfl_down_sync(0xffffffffu, p1, o);
    }
    if ((tid & 31) == 0) {
        red0[tid >> 5] = p0;
        red1[tid >> 5] = p1;
    }
    __syncthreads();

    if (tid == 0) {
        float t0 = lb[0], t1 = lb[1];
#pragma unroll
        for (int i = 0; i < 8; i++) { t0 += red0[i]; t1 += red1[i]; }

        // ---- IK: 9 damped-Newton steps (fp32; convergent iteration) ----
        const float tx = t0, ty = t1;
        float q1 = angles0[0];
        float q2 = angles0[1];
#pragma unroll
        for (int s = 0; s < 9; s++) {
            float s1, c1, s12, c12;
            sincosf(q1, &s1, &c1);
            sincosf(q1 + q2, &s12, &c12);
            float px = c1 + c12;          // L1 = L2 = 1
            float py = s1 + s12;
            float ex = tx - px, ey = ty - py;
            float j11 = -s1 - s12, j12 = -s12;
            float j21 =  c1 + c12, j22 =  c12;
            float det = j11 * j22 - j12 * j21;
            float inv = 1.0f / (det + 1e-6f);
            q1 += (j22 * ex - j12 * ey) * inv;   // ALPHA = 1
            q2 += (-j21 * ex + j11 * ey) * inv;
        }

        // ---- trajectory: start -> mid(-0.2,0) -> end(0,-0.1), 10+9 points ----
        float s1, c1, s12, c12;
        sincosf(q1, &s1, &c1);
        sincosf(q1 + q2, &s12, &c12);
        float sx = c1 + c12;
        float sy = s1 + s12;
        float mx0 = sx - 0.2f, my0 = sy;
        float ex0 = mx0,       ey0 = my0 - 0.1f;
#pragma unroll
        for (int k = 0; k < 10; k++) {
            float t = (float)k * (1.0f / 9.0f);
            out[2 * k]     = sx * (1.0f - t) + mx0 * t;
            out[2 * k + 1] = sy * (1.0f - t) + my0 * t;
        }
#pragma unroll
        for (int k = 1; k < 10; k++) {
            float t = (float)k * (1.0f / 9.0f);
            out[2 * (9 + k)]     = mx0 * (1.0f - t) + ex0 * t;
            out[2 * (9 + k) + 1] = my0 * (1.0f - t) + ey0 * t;
        }

        // ---- odometry ----
        float dl = ticks[0] * 1e-4f;
        float dr = ticks[1] * 1e-4f;
        float dc = 0.5f * (dl + dr);
        float dth = (dr - dl) * 2.0f;          // / 0.5
        float avg = pose[2] + 0.5f * dth;
        float sa, ca;
        sincosf(avg, &sa, &ca);
        out[38] = pose[0] + dc * ca;
        out[39] = pose[1] + dc * sa;
        out[40] = pose[2] + dth;
    }
}

extern "C" void kernel_launch(void* const* d_in, const int* in_sizes, int n_in,
                              void* d_out, int out_size)
{
    const float* x       = (const float*)d_in[0];
    const float* pose    = (const float*)d_in[1];
    const float* angles0 = (const float*)d_in[2];
    const float* ticks   = (const float*)d_in[3];
    const float* cw      = (const float*)d_in[4];
    const float* cb      = (const float*)d_in[5];
    const float* lw      = (const float*)d_in[6];
    const float* lb      = (const float*)d_in[7];
    float* out = (float*)d_out;

    robot_fused_kernel<<<1, 256>>>(x, pose, angles0, ticks, cw, cb, lw, lb, out);
}

// round 3
// speedup vs baseline: 3.6536x; 1.1572x over previous
#include <cuda_runtime.h>
#include <math.h>

// Fully-fused robotics pipeline, fp32, MUFU trig (tol 1e-3, iteration is
// convergent so approx trig error doesn't amplify).
//  inputs (metadata order):
//   0 sensor_input  [1,3,64,64]  (12288 f32)
//   1 initial_pose  [3]
//   2 initial_angles[2]
//   3 wheel_ticks   [2]
//   4 conv_w        [4,3,4,4]    (192)
//   5 conv_b        [4]
//   6 lin_w         [2,256]      (512)
//   7 lin_b         [2]
//  output: trajectory [19,2] then new_pose [3]  -> 41 f32

__global__ __launch_bounds__(256, 1)
void robot_fused_kernel(const float* __restrict__ x,
                        const float* __restrict__ pose,
                        const float* __restrict__ angles0,
                        const float* __restrict__ ticks,
                        const float* __restrict__ cw,
                        const float* __restrict__ cb,
                        const float* __restrict__ lw,
                        const float* __restrict__ lb,
                        float* __restrict__ out)
{
    __shared__ float red0[8];
    __shared__ float red1[8];

    const int tid = threadIdx.x;          // 0..255, one pooled output each
    const int c  = tid >> 6;              // 0..3
    const int ph = (tid >> 3) & 7;        // 0..7
    const int pw = tid & 7;               // 0..7

    // Preload this channel's 3x4x4 filter into registers
    float w[3][4][4];
#pragma unroll
    for (int ic = 0; ic < 3; ic++)
#pragma unroll
        for (int kh = 0; kh < 4; kh++)
#pragma unroll
            for (int kw = 0; kw < 4; kw++)
                w[ic][kh][kw] = cw[((c * 3 + ic) * 4 + kh) * 4 + kw];

    const float bias = cb[c];

    // conv (stride 4, pad 1) + relu + 2x2 maxpool for this pooled cell
    float mx = 0.0f;  // relu floor is 0, so max starts at 0
#pragma unroll
    for (int dy = 0; dy < 2; dy++) {
#pragma unroll
        for (int dx = 0; dx < 2; dx++) {
            const int oh = 2 * ph + dy;       // 0..15
            const int ow = 2 * pw + dx;       // 0..15
            float acc = bias;
#pragma unroll
            for (int ic = 0; ic < 3; ic++) {
                const float* xp = x + ic * 4096;
#pragma unroll
                for (int kh = 0; kh < 4; kh++) {
                    const int ih = oh * 4 - 1 + kh;
                    if (ih < 0 || ih > 63) continue;
#pragma unroll
                    for (int kw = 0; kw < 4; kw++) {
                        const int iw = ow * 4 - 1 + kw;
                        if (iw < 0 || iw > 63) continue;
                        acc = fmaf(xp[ih * 64 + iw], w[ic][kh][kw], acc);
                    }
                }
            }
            mx = fmaxf(mx, fmaxf(acc, 0.0f));
        }
    }

    // linear 256 -> 2: per-thread partials, warp shuffle reduce, smem combine
    float p0 = mx * lw[tid];
    float p1 = mx * lw[256 + tid];
#pragma unroll
    for (int o = 16; o > 0; o >>= 1) {
        p0 += __shfl_down_sync(0xffffffffu, p0, o);
        p1 += __shfl_down_sync(0xffffffffu, p1, o);
    }
    if ((tid & 31) == 0) {
        red0[tid >> 5] = p0;
        red1[tid >> 5] = p1;
    }
    __syncthreads();

    if (tid == 0) {
        float t0 = lb[0], t1 = lb[1];
#pragma unroll
        for (int i = 0; i < 8; i++) { t0 += red0[i]; t1 += red1[i]; }

        // ---- IK: 9 Newton steps, MUFU trig (convergent iteration) ----
        const float tx = t0, ty = t1;
        float q1 = angles0[0];
        float q2 = angles0[1];
#pragma unroll
        for (int s = 0; s < 9; s++) {
            float s1  = __sinf(q1),      c1  = __cosf(q1);
            float s12 = __sinf(q1 + q2), c12 = __cosf(q1 + q2);
            float px = c1 + c12;          // L1 = L2 = 1
            float py = s1 + s12;
            float ex = tx - px, ey = ty - py;
            float j11 = -s1 - s12, j12 = -s12;
            float j21 =  c1 + c12, j22 =  c12;
            float det = j11 * j22 - j12 * j21;
            float inv = 1.0f / (det + 1e-6f);
            q1 += (j22 * ex - j12 * ey) * inv;   // ALPHA = 1
            q2 += (-j21 * ex + j11 * ey) * inv;
        }

        // ---- trajectory: start -> mid(-0.2,0) -> end(0,-0.1), 10+9 points ----
        float s1  = __sinf(q1),      c1  = __cosf(q1);
        float s12 = __sinf(q1 + q2), c12 = __cosf(q1 + q2);
        float sx = c1 + c12;
        float sy = s1 + s12;
        float mx0 = sx - 0.2f, my0 = sy;
        float ex0 = mx0,       ey0 = my0 - 0.1f;
#pragma unroll
        for (int k = 0; k < 10; k++) {
            float t = (float)k * (1.0f / 9.0f);
            out[2 * k]     = sx * (1.0f - t) + mx0 * t;
            out[2 * k + 1] = sy * (1.0f - t) + my0 * t;
        }
#pragma unroll
        for (int k = 1; k < 10; k++) {
            float t = (float)k * (1.0f / 9.0f);
            out[2 * (9 + k)]     = mx0 * (1.0f - t) + ex0 * t;
            out[2 * (9 + k) + 1] = my0 * (1.0f - t) + ey0 * t;
        }

        // ---- odometry ----
        float dl = ticks[0] * 1e-4f;
        float dr = ticks[1] * 1e-4f;
        float dc = 0.5f * (dl + dr);
        float dth = (dr - dl) * 2.0f;          // / 0.5
        float avg = pose[2] + 0.5f * dth;
        out[38] = pose[0] + dc * __cosf(avg);
        out[39] = pose[1] + dc * __sinf(avg);
        out[40] = pose[2] + dth;
    }
}

extern "C" void kernel_launch(void* const* d_in, const int* in_sizes, int n_in,
                              void* d_out, int out_size)
{
    const float* x       = (const float*)d_in[0];
    const float* pose    = (const float*)d_in[1];
    const float* angles0 = (const float*)d_in[2];
    const float* ticks   = (const float*)d_in[3];
    const float* cw      = (const float*)d_in[4];
    const float* cb      = (const float*)d_in[5];
    const float* lw      = (const float*)d_in[6];
    const float* lb      = (const float*)d_in[7];
    float* out = (float*)d_out;

    robot_fused_kernel<<<1, 256>>>(x, pose, angles0, ticks, cw, cb, lw, lb, out);
}

// round 5
// speedup vs baseline: 5.9008x; 1.6151x over previous
#include <cuda_runtime.h>
#include <math.h>

// Fully-fused robotics pipeline. 256 threads = 16x16 conv output pixels,
// each thread computes all 4 output channels (shared input window).
// All input traffic is aligned float4 + shfl for the pad-1 misalignment.
//  inputs: 0 x[1,3,64,64] 1 pose[3] 2 angles[2] 3 ticks[2]
//          4 conv_w[4,3,4,4] 5 conv_b[4] 6 lin_w[2,256] 7 lin_b[2]
//  output: trajectory [19,2] then new_pose [3] -> 41 f32

__global__ __launch_bounds__(256, 1)
void robot_fused_kernel(const float* __restrict__ x,
                        const float* __restrict__ pose,
                        const float* __restrict__ angles0,
                        const float* __restrict__ ticks,
                        const float* __restrict__ cw,
                        const float* __restrict__ cb,
                        const float* __restrict__ lw,
                        const float* __restrict__ lb,
                        float* __restrict__ out)
{
    __shared__ float ws[192];        // transposed conv weights [ic][kh][kw][oc]
    __shared__ float red0[8];
    __shared__ float red1[8];

    const int tid = threadIdx.x;     // 0..255

    // Stage conv weights transposed: cw[oc][ic][kh][kw] -> ws[(ic*16+kh*4+kw)*4+oc]
    if (tid < 192) {
        int oc = tid / 48;
        int r  = tid % 48;           // ic*16 + kh*4 + kw
        ws[r * 4 + oc] = cw[tid];
    }
    __syncthreads();

    const int oh = tid >> 4;         // 0..15 conv output row
    const int ow = tid & 15;         // 0..15 conv output col
    const float4* __restrict__ x4 = (const float4*)x;   // plane = 1024 float4

    // bias (4 floats, 16B aligned)
    const float4 b4 = *(const float4*)cb;
    float acc0 = b4.x, acc1 = b4.y, acc2 = b4.z, acc3 = b4.w;

#pragma unroll
    for (int ic = 0; ic < 3; ic++) {
#pragma unroll
        for (int kh = 0; kh < 4; kh++) {
            const int ih = oh * 4 - 1 + kh;            // -1..62
            float4 f = make_float4(0.f, 0.f, 0.f, 0.f);
            if (ih >= 0) f = x4[ic * 1024 + ih * 16 + ow];
            // col ow*4-1 lives in the previous lane's .w (pad 0 at ow==0).
            float left = __shfl_up_sync(0xffffffffu, f.w, 1);
            if (ow == 0) left = 0.f;

            const float4* wp = (const float4*)&ws[(ic * 16 + kh * 4) * 4];
            const float4 w0 = wp[0], w1 = wp[1], w2 = wp[2], w3 = wp[3];
            acc0 = fmaf(left, w0.x, acc0); acc1 = fmaf(left, w0.y, acc1);
            acc2 = fmaf(left, w0.z, acc2); acc3 = fmaf(left, w0.w, acc3);
            acc0 = fmaf(f.x,  w1.x, acc0); acc1 = fmaf(f.x,  w1.y, acc1);
            acc2 = fmaf(f.x,  w1.z, acc2); acc3 = fmaf(f.x,  w1.w, acc3);
            acc0 = fmaf(f.y,  w2.x, acc0); acc1 = fmaf(f.y,  w2.y, acc1);
            acc2 = fmaf(f.y,  w2.z, acc2); acc3 = fmaf(f.y,  w2.w, acc3);
            acc0 = fmaf(f.z,  w3.x, acc0); acc1 = fmaf(f.z,  w3.y, acc1);
            acc2 = fmaf(f.z,  w3.z, acc2); acc3 = fmaf(f.z,  w3.w, acc3);
        }
    }

    // relu
    acc0 = fmaxf(acc0, 0.f); acc1 = fmaxf(acc1, 0.f);
    acc2 = fmaxf(acc2, 0.f); acc3 = fmaxf(acc3, 0.f);

    // 2x2 maxpool: ow pair = lane xor 1, oh pair = lane xor 16 (same warp)
    acc0 = fmaxf(acc0, __shfl_xor_sync(0xffffffffu, acc0, 1));
    acc1 = fmaxf(acc1, __shfl_xor_sync(0xffffffffu, acc1, 1));
    acc2 = fmaxf(acc2, __shfl_xor_sync(0xffffffffu, acc2, 1));
    acc3 = fmaxf(acc3, __shfl_xor_sync(0xffffffffu, acc3, 1));
    acc0 = fmaxf(acc0, __shfl_xor_sync(0xffffffffu, acc0, 16));
    acc1 = fmaxf(acc1, __shfl_xor_sync(0xffffffffu, acc1, 16));
    acc2 = fmaxf(acc2, __shfl_xor_sync(0xffffffffu, acc2, 16));
    acc3 = fmaxf(acc3, __shfl_xor_sync(0xffffffffu, acc3, 16));

    // linear 256->2; flatten idx = c*64 + ph*8 + pw. All 4 lanes of a pool
    // group hold identical maxima and identical (ph,pw) -> each partial is
    // counted 4x; compensate with 0.25 in the final combine.
    const int s = (oh >> 1) * 8 + (ow >> 1);
    float p0 = acc0 * lw[s]       + acc1 * lw[64 + s]
             + acc2 * lw[128 + s] + acc3 * lw[192 + s];
    float p1 = acc0 * lw[256 + s]       + acc1 * lw[256 + 64 + s]
             + acc2 * lw[256 + 128 + s] + acc3 * lw[256 + 192 + s];

#pragma unroll
    for (int o = 16; o > 0; o >>= 1) {
        p0 += __shfl_down_sync(0xffffffffu, p0, o);
        p1 += __shfl_down_sync(0xffffffffu, p1, o);
    }
    if ((tid & 31) == 0) {
        red0[tid >> 5] = p0;
        red1[tid >> 5] = p1;
    }
    __syncthreads();

    if (tid == 0) {
        float t0 = 0.f, t1 = 0.f;
#pragma unroll
        for (int i = 0; i < 8; i++) { t0 += red0[i]; t1 += red1[i]; }
        t0 = lb[0] + 0.25f * t0;
        t1 = lb[1] + 0.25f * t1;

        // ---- IK: 9 Newton steps, MUFU trig (convergent iteration) ----
        const float tx = t0, ty = t1;
        float q1 = angles0[0];
        float q2 = angles0[1];
#pragma unroll
        for (int st = 0; st < 9; st++) {
            float s1  = __sinf(q1),      c1  = __cosf(q1);
            float s12 = __sinf(q1 + q2), c12 = __cosf(q1 + q2);
            float ex = tx - (c1 + c12), ey = ty - (s1 + s12);
            float j11 = -s1 - s12, j12 = -s12;
            float j21 =  c1 + c12, j22 =  c12;
            float det = j11 * j22 - j12 * j21;
            float inv = 1.0f / (det + 1e-6f);
            q1 += (j22 * ex - j12 * ey) * inv;   // ALPHA = 1
            q2 += (-j21 * ex + j11 * ey) * inv;
        }

        // ---- trajectory: start -> mid(-0.2,0) -> end(0,-0.1), 10+9 pts ----
        float s1  = __sinf(q1),      c1  = __cosf(q1);
        float s12 = __sinf(q1 + q2), c12 = __cosf(q1 + q2);
        float sx = c1 + c12;
        float sy = s1 + s12;
        float mx0 = sx - 0.2f, my0 = sy;
        float ex0 = mx0,       ey0 = my0 - 0.1f;
#pragma unroll
        for (int k = 0; k < 10; k++) {
            float t = (float)k * (1.0f / 9.0f);
            out[2 * k]     = sx * (1.0f - t) + mx0 * t;
            out[2 * k + 1] = sy * (1.0f - t) + my0 * t;
        }
#pragma unroll
        for (int k = 1; k < 10; k++) {
            float t = (float)k * (1.0f / 9.0f);
            out[2 * (9 + k)]     = mx0 * (1.0f - t) + ex0 * t;
            out[2 * (9 + k) + 1] = my0 * (1.0f - t) + ey0 * t;
        }

        // ---- odometry ----
        float dl = ticks[0] * 1e-4f;
        float dr = ticks[1] * 1e-4f;
        float dc = 0.5f * (dl + dr);
        float dth = (dr - dl) * 2.0f;          // / AXLE_WIDTH(0.5)
        float avg = pose[2] + 0.5f * dth;
        out[38] = pose[0] + dc * __cosf(avg);
        out[39] = pose[1] + dc * __sinf(avg);
        out[40] = pose[2] + dth;
    }
}

extern "C" void kernel_launch(void* const* d_in, const int* in_sizes, int n_in,
                              void* d_out, int out_size)
{
    const float* x       = (const float*)d_in[0];
    const float* pose    = (const float*)d_in[1];
    const float* angles0 = (const float*)d_in[2];
    const float* ticks   = (const float*)d_in[3];
    const float* cw      = (const float*)d_in[4];
    const float* cb      = (const float*)d_in[5];
    const float* lw      = (const float*)d_in[6];
    const float* lb      = (const float*)d_in[7];
    float* out = (float*)d_out;

    robot_fused_kernel<<<1, 256>>>(x, pose, angles0, ticks, cw, cb, lw, lb, out);
}

// round 6
// speedup vs baseline: 6.9163x; 1.1721x over previous
#include <cuda_runtime.h>
#include <math.h>

// Fully-fused robotics pipeline. 256 threads = 16x16 conv output pixels,
// each thread computes all 4 output channels. ALL global loads issued in one
// front batch (single DRAM round trip); tail scalars prefetched on thread 0.
//  inputs: 0 x[1,3,64,64] 1 pose[3] 2 angles[2] 3 ticks[2]
//          4 conv_w[4,3,4,4] 5 conv_b[4] 6 lin_w[2,256] 7 lin_b[2]
//  output: trajectory [19,2] then new_pose [3] -> 41 f32

__global__ __launch_bounds__(256, 1)
void robot_fused_kernel(const float* __restrict__ x,
                        const float* __restrict__ pose,
                        const float* __restrict__ angles0,
                        const float* __restrict__ ticks,
                        const float* __restrict__ cw,
                        const float* __restrict__ cb,
                        const float* __restrict__ lw,
                        const float* __restrict__ lb,
                        float* __restrict__ out)
{
    __shared__ float ws[192];        // transposed conv weights [ic][kh][kw][oc]
    __shared__ float red0[8];
    __shared__ float red1[8];

    const int tid = threadIdx.x;     // 0..255
    const int oh = tid >> 4;         // 0..15 conv output row
    const int ow = tid & 15;         // 0..15 conv output col
    const float4* __restrict__ x4 = (const float4*)x;   // plane = 1024 float4
    const int s = (oh >> 1) * 8 + (ow >> 1);            // pooled flatten idx

    // ---------- FRONT BATCH: every global load, maximum MLP ----------
    // (1) input window: 12 aligned float4 loads
    float4 f[3][4];
#pragma unroll
    for (int ic = 0; ic < 3; ic++) {
#pragma unroll
        for (int kh = 0; kh < 4; kh++) {
            const int ih = oh * 4 - 1 + kh;            // -1..62
            f[ic][kh] = make_float4(0.f, 0.f, 0.f, 0.f);
            if (ih >= 0) f[ic][kh] = x4[ic * 1024 + ih * 16 + ow];
        }
    }
    // (2) linear weights for this pooled index (used after pooling)
    float lwa0 = lw[s],             lwa1 = lw[64 + s];
    float lwa2 = lw[128 + s],       lwa3 = lw[192 + s];
    float lwb0 = lw[256 + s],       lwb1 = lw[256 + 64 + s];
    float lwb2 = lw[256 + 128 + s], lwb3 = lw[256 + 192 + s];
    // (3) bias
    const float4 b4 = *(const float4*)cb;
    // (4) conv weight staging value
    float wstage = 0.f;
    if (tid < 192) wstage = cw[tid];
    // (5) tail scalars (thread 0 only)
    float q1i = 0.f, q2i = 0.f, px0 = 0.f, px1 = 0.f, px2 = 0.f;
    float tk0 = 0.f, tk1 = 0.f, lb0 = 0.f, lb1 = 0.f;
    if (tid == 0) {
        q1i = angles0[0]; q2i = angles0[1];
        px0 = pose[0]; px1 = pose[1]; px2 = pose[2];
        tk0 = ticks[0]; tk1 = ticks[1];
        lb0 = lb[0];   lb1 = lb[1];
    }

    // Stage conv weights transposed: cw[oc][ic][kh][kw] -> ws[r*4+oc]
    if (tid < 192) {
        int oc = tid / 48;
        int r  = tid % 48;           // ic*16 + kh*4 + kw
        ws[r * 4 + oc] = wstage;
    }
    __syncthreads();

    // ---------- conv + relu + pool ----------
    float acc0 = b4.x, acc1 = b4.y, acc2 = b4.z, acc3 = b4.w;
#pragma unroll
    for (int ic = 0; ic < 3; ic++) {
#pragma unroll
        for (int kh = 0; kh < 4; kh++) {
            const float4 v = f[ic][kh];
            // col ow*4-1 lives in the previous lane's .w (pad 0 at ow==0).
            float left = __shfl_up_sync(0xffffffffu, v.w, 1);
            if (ow == 0) left = 0.f;

            const float4* wp = (const float4*)&ws[(ic * 16 + kh * 4) * 4];
            const float4 w0 = wp[0], w1 = wp[1], w2 = wp[2], w3 = wp[3];
            acc0 = fmaf(left, w0.x, acc0); acc1 = fmaf(left, w0.y, acc1);
            acc2 = fmaf(left, w0.z, acc2); acc3 = fmaf(left, w0.w, acc3);
            acc0 = fmaf(v.x,  w1.x, acc0); acc1 = fmaf(v.x,  w1.y, acc1);
            acc2 = fmaf(v.x,  w1.z, acc2); acc3 = fmaf(v.x,  w1.w, acc3);
            acc0 = fmaf(v.y,  w2.x, acc0); acc1 = fmaf(v.y,  w2.y, acc1);
            acc2 = fmaf(v.y,  w2.z, acc2); acc3 = fmaf(v.y,  w2.w, acc3);
            acc0 = fmaf(v.z,  w3.x, acc0); acc1 = fmaf(v.z,  w3.y, acc1);
            acc2 = fmaf(v.z,  w3.z, acc2); acc3 = fmaf(v.z,  w3.w, acc3);
        }
    }

    acc0 = fmaxf(acc0, 0.f); acc1 = fmaxf(acc1, 0.f);
    acc2 = fmaxf(acc2, 0.f); acc3 = fmaxf(acc3, 0.f);

    // 2x2 maxpool: ow pair = lane xor 1, oh pair = lane xor 16 (same warp)
    acc0 = fmaxf(acc0, __shfl_xor_sync(0xffffffffu, acc0, 1));
    acc1 = fmaxf(acc1, __shfl_xor_sync(0xffffffffu, acc1, 1));
    acc2 = fmaxf(acc2, __shfl_xor_sync(0xffffffffu, acc2, 1));
    acc3 = fmaxf(acc3, __shfl_xor_sync(0xffffffffu, acc3, 1));
    acc0 = fmaxf(acc0, __shfl_xor_sync(0xffffffffu, acc0, 16));
    acc1 = fmaxf(acc1, __shfl_xor_sync(0xffffffffu, acc1, 16));
    acc2 = fmaxf(acc2, __shfl_xor_sync(0xffffffffu, acc2, 16));
    acc3 = fmaxf(acc3, __shfl_xor_sync(0xffffffffu, acc3, 16));

    // linear partials (each pooled cell counted 4x; 0.25 compensation below)
    float p0 = acc0 * lwa0 + acc1 * lwa1 + acc2 * lwa2 + acc3 * lwa3;
    float p1 = acc0 * lwb0 + acc1 * lwb1 + acc2 * lwb2 + acc3 * lwb3;

#pragma unroll
    for (int o = 16; o > 0; o >>= 1) {
        p0 += __shfl_down_sync(0xffffffffu, p0, o);
        p1 += __shfl_down_sync(0xffffffffu, p1, o);
    }
    if ((tid & 31) == 0) {
        red0[tid >> 5] = p0;
        red1[tid >> 5] = p1;
    }
    __syncthreads();

    if (tid == 0) {
        float t0 = 0.f, t1 = 0.f;
#pragma unroll
        for (int i = 0; i < 8; i++) { t0 += red0[i]; t1 += red1[i]; }
        t0 = lb0 + 0.25f * t0;
        t1 = lb1 + 0.25f * t1;

        // ---- IK: 9 Newton steps, MUFU trig + fast division ----
        const float tx = t0, ty = t1;
        float q1 = q1i, q2 = q2i;
#pragma unroll
        for (int st = 0; st < 9; st++) {
            float s1  = __sinf(q1),      c1  = __cosf(q1);
            float s12 = __sinf(q1 + q2), c12 = __cosf(q1 + q2);
            float ex = tx - (c1 + c12), ey = ty - (s1 + s12);
            float j11 = -s1 - s12, j12 = -s12;
            float j21 =  c1 + c12, j22 =  c12;
            float det = j11 * j22 - j12 * j21;
            float inv = __fdividef(1.0f, det + 1e-6f);
            q1 += (j22 * ex - j12 * ey) * inv;   // ALPHA = 1
            q2 += (-j21 * ex + j11 * ey) * inv;
        }

        // ---- trajectory: start -> mid(-0.2,0) -> end(0,-0.1), 10+9 pts ----
        float s1  = __sinf(q1),      c1  = __cosf(q1);
        float s12 = __sinf(q1 + q2), c12 = __cosf(q1 + q2);
        float sx = c1 + c12;
        float sy = s1 + s12;
        float mx0 = sx - 0.2f, my0 = sy;
        float ex0 = mx0,       ey0 = my0 - 0.1f;
#pragma unroll
        for (int k = 0; k < 10; k++) {
            float t = (float)k * (1.0f / 9.0f);
            out[2 * k]     = sx * (1.0f - t) + mx0 * t;
            out[2 * k + 1] = sy * (1.0f - t) + my0 * t;
        }
#pragma unroll
        for (int k = 1; k < 10; k++) {
            float t = (float)k * (1.0f / 9.0f);
            out[2 * (9 + k)]     = mx0 * (1.0f - t) + ex0 * t;
            out[2 * (9 + k) + 1] = my0 * (1.0f - t) + ey0 * t;
        }

        // ---- odometry ----
        float dl = tk0 * 1e-4f;
        float dr = tk1 * 1e-4f;
        float dc = 0.5f * (dl + dr);
        float dth = (dr - dl) * 2.0f;          // / AXLE_WIDTH(0.5)
        float avg = px2 + 0.5f * dth;
        out[38] = px0 + dc * __cosf(avg);
        out[39] = px1 + dc * __sinf(avg);
        out[40] = px2 + dth;
    }
}

extern "C" void kernel_launch(void* const* d_in, const int* in_sizes, int n_in,
                              void* d_out, int out_size)
{
    const float* x       = (const float*)d_in[0];
    const float* pose    = (const float*)d_in[1];
    const float* angles0 = (const float*)d_in[2];
    const float* ticks   = (const float*)d_in[3];
    const float* cw      = (const float*)d_in[4];
    const float* cb      = (const float*)d_in[5];
    const float* lw      = (const float*)d_in[6];
    const float* lb      = (const float*)d_in[7];
    float* out = (float*)d_out;

    robot_fused_kernel<<<1, 256>>>(x, pose, angles0, ticks, cw, cb, lw, lb, out);
}